// round 1
// baseline (speedup 1.0000x reference)
#include <cuda_runtime.h>
#include <cuda_fp16.h>
#include <cstdint>

#define N_EDGES  2000000
#define NUM_SEGS 500000
#define HID      128
#define NRB      4
#define TILE_M   128
#define NTILES   (N_EDGES / TILE_M)   /* 15625 exact */
#define WSTRIDE  136                  /* halves per W row: 128 + 8 pad -> conflict-free ldmatrix */
#define RMS_EPS  1.1920928955078125e-07f

/* SMEM layout (bytes) */
#define OFF_W     0
#define SZ_W      (NRB * HID * WSTRIDE * 2)          /* 139264 */
#define OFF_WINB  (OFF_W + SZ_W)                     /* float4[128] */
#define OFF_BRES  (OFF_WINB + HID * 16)              /* float[4*128] */
#define OFF_WOUT  (OFF_BRES + NRB * HID * 4)         /* float[128] */
#define OFF_XS    (OFF_WOUT + HID * 4)               /* float4[128] */
#define SMEM_BYTES (OFF_XS + TILE_M * 16)            /* 145920 */

__device__ float    g_logits[N_EDGES];
__device__ unsigned g_segmax[NUM_SEGS];
__device__ float    g_segsum[NUM_SEGS];

__device__ __forceinline__ unsigned enc_f(float f) {
    unsigned b = __float_as_uint(f);
    return (b & 0x80000000u) ? ~b : (b | 0x80000000u);
}
__device__ __forceinline__ float dec_f(unsigned k) {
    unsigned b = (k & 0x80000000u) ? (k & 0x7FFFFFFFu) : ~k;
    return __uint_as_float(b);
}
__device__ __forceinline__ uint32_t pack_h2(float lo, float hi) {
    __half2 h = __floats2half2_rn(lo, hi);
    return *reinterpret_cast<uint32_t*>(&h);
}
__device__ __forceinline__ void ldsm_x2(uint32_t& r0, uint32_t& r1, uint32_t addr) {
    asm volatile("ldmatrix.sync.aligned.m8n8.x2.shared.b16 {%0,%1}, [%2];\n"
                 : "=r"(r0), "=r"(r1) : "r"(addr));
}
__device__ __forceinline__ void mma16816(float* d,
        uint32_t a0, uint32_t a1, uint32_t a2, uint32_t a3,
        uint32_t b0, uint32_t b1) {
    asm volatile("mma.sync.aligned.m16n8k16.row.col.f32.f16.f16.f32 "
                 "{%0,%1,%2,%3}, {%4,%5,%6,%7}, {%8,%9}, {%0,%1,%2,%3};\n"
                 : "+f"(d[0]), "+f"(d[1]), "+f"(d[2]), "+f"(d[3])
                 : "r"(a0), "r"(a1), "r"(a2), "r"(a3), "r"(b0), "r"(b1));
}

__global__ void __launch_bounds__(256, 1)
mlp_kernel(const float* __restrict__ ef, const int* __restrict__ ids,
           const float* __restrict__ W_in, const float* __restrict__ b_in,
           const float* __restrict__ rms_w, const float* __restrict__ W_res,
           const float* __restrict__ b_res, const float* __restrict__ W_out,
           const float* __restrict__ b_out)
{
    extern __shared__ char smem[];
    __half* Wh   = (__half*)(smem + OFF_W);
    float4* winb = (float4*)(smem + OFF_WINB);
    float*  brs  = (float*)(smem + OFF_BRES);
    float*  wout = (float*)(smem + OFF_WOUT);
    float4* xs   = (float4*)(smem + OFF_XS);

    const int tid = threadIdx.x;

    /* ---- stage weights once per CTA; fold rms_w (per-k) into W_res ---- */
    for (int idx = tid; idx < NRB * HID * HID; idx += 256) {
        int i   = idx >> 14;          /* / (128*128) */
        int rem = idx & 16383;
        int n   = rem >> 7;
        int k   = rem & 127;
        float w = W_res[idx] * rms_w[i * HID + k];
        Wh[(i * HID + n) * WSTRIDE + k] = __float2half(w);
    }
    for (int c = tid; c < HID; c += 256) {
        winb[c] = make_float4(W_in[c * 3], W_in[c * 3 + 1], W_in[c * 3 + 2], b_in[c]);
        wout[c] = W_out[c];
    }
    for (int idx = tid; idx < NRB * HID; idx += 256) brs[idx] = b_res[idx];
    __syncthreads();

    const float bout = b_out[0];
    const int warp = tid >> 5, lane = tid & 31;
    const int q = lane & 3, gid = lane >> 2;

    uint32_t wbase = (uint32_t)__cvta_generic_to_shared(Wh);
    /* ldmatrix.x2: lanes 0-7 -> rows n (k chunk 0), lanes 8-15 -> rows n (k chunk +8 halves) */
    uint32_t laneB = wbase + (((lane & 7) * WSTRIDE) + ((lane >> 3) & 1) * 8) * 2;

    for (int tile = blockIdx.x; tile < NTILES; tile += gridDim.x) {
        __syncthreads();
        if (tid < TILE_M) {
            long r = (long)tile * TILE_M + tid;
            xs[tid] = make_float4(ef[r * 3], ef[r * 3 + 1], ef[r * 3 + 2], 0.f);
        }
        __syncthreads();

        /* ---- input layer, directly in C-fragment layout ----
           hc[j][0]=(row gid,   col 8j+2q)  hc[j][1]=(row gid,   col 8j+2q+1)
           hc[j][2]=(row gid+8, col 8j+2q)  hc[j][3]=(row gid+8, col 8j+2q+1) */
        float hc[16][4];
        {
            float4 x0 = xs[warp * 16 + gid];
            float4 x1 = xs[warp * 16 + gid + 8];
            #pragma unroll
            for (int j = 0; j < 16; j++) {
                float4 w0 = winb[j * 8 + q * 2];
                float4 w1 = winb[j * 8 + q * 2 + 1];
                hc[j][0] = w0.w + x0.x * w0.x + x0.y * w0.y + x0.z * w0.z;
                hc[j][1] = w1.w + x0.x * w1.x + x0.y * w1.y + x0.z * w1.z;
                hc[j][2] = w0.w + x1.x * w0.x + x1.y * w0.y + x1.z * w0.z;
                hc[j][3] = w1.w + x1.x * w1.x + x1.y * w1.y + x1.z * w1.z;
            }
        }

        /* ---- 4 residual blocks, activations never leave registers ---- */
        #pragma unroll
        for (int blk = 0; blk < NRB; blk++) {
            float ss0 = 0.f, ss1 = 0.f;
            #pragma unroll
            for (int j = 0; j < 16; j++) {
                ss0 += hc[j][0] * hc[j][0] + hc[j][1] * hc[j][1];
                ss1 += hc[j][2] * hc[j][2] + hc[j][3] * hc[j][3];
            }
            ss0 += __shfl_xor_sync(0xffffffffu, ss0, 1);
            ss0 += __shfl_xor_sync(0xffffffffu, ss0, 2);
            ss1 += __shfl_xor_sync(0xffffffffu, ss1, 1);
            ss1 += __shfl_xor_sync(0xffffffffu, ss1, 2);
            float s0 = rsqrtf(ss0 * (1.f / HID) + RMS_EPS);
            float s1 = rsqrtf(ss1 * (1.f / HID) + RMS_EPS);

            float y[16][4];
            #pragma unroll
            for (int j = 0; j < 16; j++)
                y[j][0] = y[j][1] = y[j][2] = y[j][3] = 0.f;

            uint32_t lb = laneB + blk * (HID * WSTRIDE * 2);
            #pragma unroll
            for (int ks = 0; ks < 8; ks++) {
                /* A fragment for k-step ks built on the fly from C tiles 2ks, 2ks+1 */
                int j0 = 2 * ks, j1 = 2 * ks + 1;
                uint32_t a0 = pack_h2(hc[j0][0] * s0, hc[j0][1] * s0);
                uint32_t a1 = pack_h2(hc[j0][2] * s1, hc[j0][3] * s1);
                uint32_t a2 = pack_h2(hc[j1][0] * s0, hc[j1][1] * s0);
                uint32_t a3 = pack_h2(hc[j1][2] * s1, hc[j1][3] * s1);
                #pragma unroll
                for (int j = 0; j < 16; j++) {
                    uint32_t b0, b1;
                    ldsm_x2(b0, b1, lb + (uint32_t)((j * 8 * WSTRIDE + ks * 16) * 2));
                    mma16816(y[j], a0, a1, a2, a3, b0, b1);
                }
            }

            const float2* br2 = (const float2*)(brs + blk * HID);
            #pragma unroll
            for (int j = 0; j < 16; j++) {
                float2 bb = br2[j * 4 + q];
                hc[j][0] += fmaxf(y[j][0] + bb.x, 0.f);
                hc[j][1] += fmaxf(y[j][1] + bb.y, 0.f);
                hc[j][2] += fmaxf(y[j][2] + bb.x, 0.f);
                hc[j][3] += fmaxf(y[j][3] + bb.y, 0.f);
            }
        }

        /* ---- output layer + fused segment-max ---- */
        float a0 = 0.f, a1 = 0.f;
        const float2* w2 = (const float2*)wout;
        #pragma unroll
        for (int j = 0; j < 16; j++) {
            float2 w = w2[j * 4 + q];
            a0 += hc[j][0] * w.x + hc[j][1] * w.y;
            a1 += hc[j][2] * w.x + hc[j][3] * w.y;
        }
        a0 += __shfl_xor_sync(0xffffffffu, a0, 1);
        a0 += __shfl_xor_sync(0xffffffffu, a0, 2);
        a1 += __shfl_xor_sync(0xffffffffu, a1, 1);
        a1 += __shfl_xor_sync(0xffffffffu, a1, 2);
        if (q == 0) {
            int r0 = tile * TILE_M + warp * 16 + gid;
            int r1 = r0 + 8;
            float l0 = a0 + bout, l1 = a1 + bout;
            g_logits[r0] = l0;
            g_logits[r1] = l1;
            atomicMax(&g_segmax[ids[r0]], enc_f(l0));
            atomicMax(&g_segmax[ids[r1]], enc_f(l1));
        }
    }
}

__global__ void init_kernel() {
    int i = blockIdx.x * blockDim.x + threadIdx.x;
    if (i < NUM_SEGS) { g_segmax[i] = 0u; g_segsum[i] = 0.f; }
}

__global__ void exp_kernel(const int* __restrict__ ids, float* __restrict__ out) {
    int i = blockIdx.x * blockDim.x + threadIdx.x;
    if (i < N_EDGES) {
        int s = ids[i];
        float m = dec_f(g_segmax[s]);
        float e = expf(g_logits[i] - m);
        out[i] = e;
        atomicAdd(&g_segsum[s], e);
    }
}

__global__ void norm_kernel(const int* __restrict__ ids, float* __restrict__ out) {
    int i = blockIdx.x * blockDim.x + threadIdx.x;
    if (i < N_EDGES) out[i] = out[i] / g_segsum[ids[i]];
}

extern "C" void kernel_launch(void* const* d_in, const int* in_sizes, int n_in,
                              void* d_out, int out_size)
{
    const float* ef    = (const float*)d_in[0];
    const int*   ids   = (const int*)d_in[1];
    const float* W_in  = (const float*)d_in[2];
    const float* b_in  = (const float*)d_in[3];
    const float* rms_w = (const float*)d_in[4];
    const float* W_res = (const float*)d_in[5];
    const float* b_res = (const float*)d_in[6];
    const float* W_out = (const float*)d_in[7];
    const float* b_out = (const float*)d_in[8];
    float* out = (float*)d_out;

    cudaFuncSetAttribute(mlp_kernel, cudaFuncAttributeMaxDynamicSharedMemorySize, SMEM_BYTES);

    int dev = 0, sms = 148;
    cudaGetDevice(&dev);
    cudaDeviceGetAttribute(&sms, cudaDevAttrMultiProcessorCount, dev);
    if (sms <= 0) sms = 148;

    init_kernel<<<(NUM_SEGS + 255) / 256, 256>>>();
    mlp_kernel<<<sms, 256, SMEM_BYTES>>>(ef, ids, W_in, b_in, rms_w,
                                         W_res, b_res, W_out, b_out);
    exp_kernel<<<(N_EDGES + 255) / 256, 256>>>(ids, out);
    norm_kernel<<<(N_EDGES + 255) / 256, 256>>>(ids, out);
}